// round 4
// baseline (speedup 1.0000x reference)
#include <cuda_runtime.h>
#include <cuda_fp16.h>

typedef unsigned long long ull;

#define BB   8
#define MM   4096
#define NN   16384
#define HH   128
#define WW   128
#define BN   (BB*NN)
#define TAUF 0.01f
#define EPSF 1e-8f
#define ITERS 100

#define KC1   8          // gemv1 K-chunks (2048 cols each)
#define RB2   32         // gemv2 row-blocks (128 rows each)

// ---------------- device state (no allocations allowed) ----------------
__device__ __half g_Ah[(size_t)MM * NN];          // A in fp16, 128 MB
__device__ float  g_x[BN];
__device__ float  g_xbar[BN];
__device__ float  g_t[BN];
__device__ float  g_yb[2][2][BN];                 // ping-pong y
__device__ float  g_rpart[KC1][MM][BB];           // phase-1 K-split partials
__device__ float  g_gpart[(size_t)RB2 * BB * NN]; // phase-2 M-split partials (16 MB)

// ---------------- packed f32x2 helpers ----------------
__device__ __forceinline__ ull pack2(float x, float y) {
    ull r;
    asm("mov.b64 %0, {%1, %2};" : "=l"(r) : "f"(x), "f"(y));
    return r;
}
__device__ __forceinline__ float2 unpack2(ull v) {
    float x, y;
    asm("mov.b64 {%0, %1}, %2;" : "=f"(x), "=f"(y) : "l"(v));
    return make_float2(x, y);
}
__device__ __forceinline__ ull fma2(ull a, ull b, ull c) {
    ull d;
    asm("fma.rn.f32x2 %0, %1, %2, %3;" : "=l"(d) : "l"(a), "l"(b), "l"(c));
    return d;
}
__device__ __forceinline__ ull h2u_to_f32x2(unsigned u) {
    __half2 h = *reinterpret_cast<__half2*>(&u);
    float2 f = __half22float2(h);
    return pack2(f.x, f.y);
}

// ---------------- A fp32 -> fp16 conversion ----------------
__global__ void k_convert(const float* __restrict__ A) {
    size_t gid = (size_t)blockIdx.x * blockDim.x + threadIdx.x;
    size_t base = gid * 8;
    float4 a = *reinterpret_cast<const float4*>(A + base);
    float4 b = *reinterpret_cast<const float4*>(A + base + 4);
    __half2 h0 = __floats2half2_rn(a.x, a.y);
    __half2 h1 = __floats2half2_rn(a.z, a.w);
    __half2 h2 = __floats2half2_rn(b.x, b.y);
    __half2 h3 = __floats2half2_rn(b.z, b.w);
    uint4 o;
    o.x = *reinterpret_cast<unsigned*>(&h0);
    o.y = *reinterpret_cast<unsigned*>(&h1);
    o.z = *reinterpret_cast<unsigned*>(&h2);
    o.w = *reinterpret_cast<unsigned*>(&h3);
    reinterpret_cast<uint4*>(g_Ah)[gid] = o;
}

// ---------------- zero init ----------------
__global__ void k_zero() {
    int idx = blockIdx.x * blockDim.x + threadIdx.x;
    if (idx < BN) {
        g_x[idx] = 0.f; g_xbar[idx] = 0.f;
        g_yb[0][0][idx] = 0.f; g_yb[0][1][idx] = 0.f;
    }
}

// ---------------- TV stencil ----------------
__global__ void k_tv(int bi) {
    int idx = blockIdx.x * blockDim.x + threadIdx.x;
    if (idx >= BN) return;
    int p = idx & (NN - 1);
    int i = p >> 7;
    int j = p & 127;

    const float* yx = g_yb[bi][0];
    const float* yy = g_yb[bi][1];
    float*       oyx = g_yb[bi ^ 1][0];
    float*       oyy = g_yb[bi ^ 1][1];

    float yxv = yx[idx];
    float yyv = yy[idx];

    float dx = (j > 0)  ? (yxv - yx[idx - 1])  : 0.f;
    float dy = (i > 0)  ? (yyv - yy[idx - WW]) : 0.f;
    g_t[idx] = g_x[idx] - TAUF * (dx + dy);

    float xb = g_xbar[idx];
    float gx = (j < WW - 1) ? (xb - g_xbar[idx + 1])  : 0.f;
    float gy = (i < HH - 1) ? (xb - g_xbar[idx + WW]) : 0.f;

    float nyx = yxv + TAUF * gx;
    float nyy = yyv + TAUF * gy;
    float denom = fmaxf(fabsf(nyx), fabsf(nyy)) + EPSF;
    float inv = 1.f / denom;
    oyx[idx] = nyx * inv;
    oyy[idx] = nyy * inv;
}

// ---------------- phase 1: rpart[kc][i][b] = sum_{j in chunk} A[i][j]*t[b][j] ----
// grid (MM/32, KC1); 256 threads; warp = 4 rows; lane owns 8 consecutive cols.
// Chunk = 2048 cols = 4 tiles of 512 cols; double-buffered smem t tiles
// (swizzled f32x2 pairs, conflict-free LDS.64); A loads double-buffered in regs.
__global__ __launch_bounds__(256, 2) void k_gemv1() {
    __shared__ ull ts[2][8 * 256];       // 2 x 16 KB
    int tid = threadIdx.x;
    int lane = tid & 31;
    int g = tid >> 5;
    int r0 = blockIdx.x * 32 + g * 4;
    int k0 = blockIdx.y * 2048;

    const __half* ap = g_Ah + (size_t)r0 * NN + k0;

    ull acc[4][8];
#pragma unroll
    for (int rr = 0; rr < 4; rr++)
#pragma unroll
        for (int b = 0; b < 8; b++) acc[rr][b] = 0ull;

    const int Xsw = (lane >> 2) & 3;     // pair swizzle for compute lanes
    const int bstage = g;                // warp g stages batch g

    float4 st[4];                        // t staging registers
    uint4  av[2][4];                     // A double buffer (4 rows each)

    // --- t tile load / store helpers (inline) ---
    // tile has 512 cols = 128 float4 per batch; lane q-th float4 at lane+32q
#define LDT(TILE)                                                             \
    {                                                                         \
        int kt = k0 + (TILE) * 512;                                           \
        _Pragma("unroll")                                                     \
        for (int q = 0; q < 4; q++)                                           \
            st[q] = *reinterpret_cast<const float4*>(                         \
                &g_t[bstage * NN + kt + (lane + q * 32) * 4]);                \
    }
#define STT(BUF)                                                              \
    {                                                                         \
        _Pragma("unroll")                                                     \
        for (int q = 0; q < 4; q++) {                                         \
            int P0 = (lane + q * 32) * 2;                                     \
            int P0s = P0 ^ ((P0 >> 4) & 3);                                   \
            int P1 = P0 + 1;                                                  \
            int P1s = P1 ^ ((P1 >> 4) & 3);                                   \
            ts[BUF][bstage * 256 + P0s] = pack2(st[q].x, st[q].y);            \
            ts[BUF][bstage * 256 + P1s] = pack2(st[q].z, st[q].w);            \
        }                                                                     \
    }
#define ALOAD(DST, SS)                                                        \
    {                                                                         \
        int col = (SS) * 256 + lane * 8;                                      \
        _Pragma("unroll")                                                     \
        for (int rr = 0; rr < 4; rr++)                                        \
            av[DST][rr] = *reinterpret_cast<const uint4*>(                    \
                ap + (size_t)rr * NN + col);                                  \
    }

    LDT(0);
    STT(0);
    ALOAD(0, 0);
    __syncthreads();

    // 8 s-steps of 256 cols; tile = ss>>1, smem buffer = tile&1
    for (int ss = 0; ss < 8; ss++) {
        int tile = ss >> 1;
        if (ss < 7) { ALOAD((ss + 1) & 1, ss + 1); }        // DRAM prefetch
        if ((ss & 1) == 0 && tile < 3) { LDT(tile + 1); }   // L2 prefetch for staging

        const uint4* a = av[ss & 1];
        int srow = ss & 1;
        int Pbase = srow * 128 + lane * 4;
        int buf = tile & 1;

#pragma unroll
        for (int p = 0; p < 4; p++) {
            int Ps = (Pbase + p) ^ Xsw;
            unsigned ua0 = (p == 0) ? a[0].x : (p == 1) ? a[0].y : (p == 2) ? a[0].z : a[0].w;
            unsigned ua1 = (p == 0) ? a[1].x : (p == 1) ? a[1].y : (p == 2) ? a[1].z : a[1].w;
            unsigned ua2 = (p == 0) ? a[2].x : (p == 1) ? a[2].y : (p == 2) ? a[2].z : a[2].w;
            unsigned ua3 = (p == 0) ? a[3].x : (p == 1) ? a[3].y : (p == 2) ? a[3].z : a[3].w;
            ull a20 = h2u_to_f32x2(ua0);
            ull a21 = h2u_to_f32x2(ua1);
            ull a22 = h2u_to_f32x2(ua2);
            ull a23 = h2u_to_f32x2(ua3);
#pragma unroll
            for (int b = 0; b < 8; b++) {
                ull tv = ts[buf][b * 256 + Ps];
                acc[0][b] = fma2(a20, tv, acc[0][b]);
                acc[1][b] = fma2(a21, tv, acc[1][b]);
                acc[2][b] = fma2(a22, tv, acc[2][b]);
                acc[3][b] = fma2(a23, tv, acc[3][b]);
            }
        }

        if ((ss & 1) == 1 && tile < 3) {  // stage next tile into other buffer
            STT((tile + 1) & 1);
            __syncthreads();
        }
    }
#undef LDT
#undef STT
#undef ALOAD

#pragma unroll
    for (int rr = 0; rr < 4; rr++) {
#pragma unroll
        for (int b = 0; b < 8; b++) {
            float2 f = unpack2(acc[rr][b]);
            float v = f.x + f.y;
            v += __shfl_xor_sync(0xffffffffu, v, 16);
            v += __shfl_xor_sync(0xffffffffu, v, 8);
            v += __shfl_xor_sync(0xffffffffu, v, 4);
            v += __shfl_xor_sync(0xffffffffu, v, 2);
            v += __shfl_xor_sync(0xffffffffu, v, 1);
            if (lane == 0)
                g_rpart[blockIdx.y][r0 + rr][b] = v;
        }
    }
}

// ---------------- phase 2: gpart[blk][b][j] = sum_{i in block} r[b][i]*A[i][j] ----
// grid (NN/1024, RB2); 128 threads; thread owns 8 consecutive cols.
// A loads double-buffered in regs; r broadcast from smem.
__global__ __launch_bounds__(128, 5) void k_gemv2(const float* __restrict__ meas) {
    __shared__ ull r2s[128 * 8];          // (row, batch) -> (r,r) packed, 8 KB
    int tid = threadIdx.x;
    int c0 = blockIdx.x * 1024;
    int i0 = blockIdx.y * 128;

#pragma unroll
    for (int k = 0; k < 8; k++) {
        int e = tid + k * 128;            // e = il*8 + b, 1024 entries
        int il = e >> 3, b = e & 7;
        int i = i0 + il;
        float v = -meas[b * MM + i];
#pragma unroll
        for (int kc = 0; kc < KC1; kc++) v += g_rpart[kc][i][b];
        r2s[e] = pack2(v, v);
    }
    __syncthreads();

    const __half* apc = g_Ah + (size_t)i0 * NN + c0 + tid * 8;

    ull acc[4][8];
#pragma unroll
    for (int q = 0; q < 4; q++)
#pragma unroll
        for (int b = 0; b < 8; b++) acc[q][b] = 0ull;

    uint4 u[2];
    u[0] = *reinterpret_cast<const uint4*>(apc);

#pragma unroll 2
    for (int i = 0; i < 128; i++) {
        if (i < 127)
            u[(i + 1) & 1] = *reinterpret_cast<const uint4*>(apc + (size_t)(i + 1) * NN);
        uint4 cu = u[i & 1];
        ull a0 = h2u_to_f32x2(cu.x);
        ull a1 = h2u_to_f32x2(cu.y);
        ull a2 = h2u_to_f32x2(cu.z);
        ull a3 = h2u_to_f32x2(cu.w);
        const ull* rrow = &r2s[i * 8];
#pragma unroll
        for (int b = 0; b < 8; b++) {
            ull rv = rrow[b];             // broadcast LDS
            acc[0][b] = fma2(a0, rv, acc[0][b]);
            acc[1][b] = fma2(a1, rv, acc[1][b]);
            acc[2][b] = fma2(a2, rv, acc[2][b]);
            acc[3][b] = fma2(a3, rv, acc[3][b]);
        }
    }

    int c = c0 + tid * 8;
#pragma unroll
    for (int b = 0; b < 8; b++) {
        float2 f0 = unpack2(acc[0][b]);
        float2 f1 = unpack2(acc[1][b]);
        float2 f2 = unpack2(acc[2][b]);
        float2 f3 = unpack2(acc[3][b]);
        float* dst = &g_gpart[((size_t)(blockIdx.y * 8 + b)) * NN + c];
        *reinterpret_cast<float4*>(dst)     = make_float4(f0.x, f0.y, f1.x, f1.y);
        *reinterpret_cast<float4*>(dst + 4) = make_float4(f2.x, f2.y, f3.x, f3.y);
    }
}

// ---------------- finish: x = t - grad ; xbar = 2x - xbar_old ----------------
__global__ void k_fin() {
    int idx = blockIdx.x * blockDim.x + threadIdx.x;
    if (idx >= BN) return;
    int b = idx >> 14;
    int j = idx & (NN - 1);
    float s = 0.f;
#pragma unroll
    for (int blk = 0; blk < RB2; blk++)
        s += g_gpart[((size_t)(blk * 8 + b)) * NN + j];
    float xn = g_t[idx] - s;
    float xbo = g_xbar[idx];
    g_x[idx] = xn;
    g_xbar[idx] = 2.f * xn - xbo;
}

// ---------------- output copy ----------------
__global__ void k_copy(float* __restrict__ out) {
    int idx = blockIdx.x * blockDim.x + threadIdx.x;
    if (idx < BN) out[idx] = g_x[idx];
}

// ---------------- launch ----------------
extern "C" void kernel_launch(void* const* d_in, const int* in_sizes, int n_in,
                              void* d_out, int out_size) {
    const float* meas = (const float*)d_in[0];
    const float* A    = (const float*)d_in[1];
    if (n_in >= 2 && in_sizes[0] != BB * MM) {
        meas = (const float*)d_in[1];
        A    = (const float*)d_in[0];
    }
    float* out = (float*)d_out;

    k_convert<<<(int)(((size_t)MM * NN) / 8 / 256), 256>>>(A);
    k_zero<<<BN / 256, 256>>>();

    for (int it = 0; it < ITERS; it++) {
        int bi = it & 1;
        k_tv<<<BN / 256, 256>>>(bi);
        k_gemv1<<<dim3(MM / 32, KC1), 256>>>();
        k_gemv2<<<dim3(NN / 1024, RB2), 128>>>(meas);
        k_fin<<<BN / 256, 256>>>();
    }
    k_copy<<<BN / 256, 256>>>(out);
}

// round 5
// speedup vs baseline: 1.4576x; 1.4576x over previous
#include <cuda_runtime.h>
#include <cuda_fp16.h>

typedef unsigned long long ull;

#define BB   8
#define MM   4096
#define NN   16384
#define HH   128
#define WW   128
#define BN   (BB*NN)
#define TAUF 0.01f
#define EPSF 1e-8f
#define ITERS 100

#define KC1   4          // gemv1 K-chunks (4096 cols each)
#define RB2   32         // gemv2 row-blocks (128 rows each)

// ---------------- device state (no allocations allowed) ----------------
__device__ __half g_Ah[(size_t)MM * NN];          // A in fp16, 128 MB
__device__ float  g_x[BN];
__device__ float  g_xbar[BN];
__device__ float  g_t[BN];
__device__ float  g_yb[2][2][BN];                 // ping-pong y
__device__ float  g_rpart[KC1][MM][BB];           // phase-1 K-split partials
__device__ float  g_gpart[(size_t)RB2 * BB * NN]; // phase-2 M-split partials (16 MB)

// ---------------- packed f32x2 helpers ----------------
__device__ __forceinline__ ull pack2(float x, float y) {
    ull r;
    asm("mov.b64 %0, {%1, %2};" : "=l"(r) : "f"(x), "f"(y));
    return r;
}
__device__ __forceinline__ float2 unpack2(ull v) {
    float x, y;
    asm("mov.b64 {%0, %1}, %2;" : "=f"(x), "=f"(y) : "l"(v));
    return make_float2(x, y);
}
__device__ __forceinline__ ull fma2(ull a, ull b, ull c) {
    ull d;
    asm("fma.rn.f32x2 %0, %1, %2, %3;" : "=l"(d) : "l"(a), "l"(b), "l"(c));
    return d;
}
__device__ __forceinline__ ull h2u_to_f32x2(unsigned u) {
    __half2 h = *reinterpret_cast<__half2*>(&u);
    float2 f = __half22float2(h);
    return pack2(f.x, f.y);
}

// ---------------- A fp32 -> fp16 conversion ----------------
__global__ void k_convert(const float* __restrict__ A) {
    size_t gid = (size_t)blockIdx.x * blockDim.x + threadIdx.x;
    size_t base = gid * 8;
    float4 a = *reinterpret_cast<const float4*>(A + base);
    float4 b = *reinterpret_cast<const float4*>(A + base + 4);
    __half2 h0 = __floats2half2_rn(a.x, a.y);
    __half2 h1 = __floats2half2_rn(a.z, a.w);
    __half2 h2 = __floats2half2_rn(b.x, b.y);
    __half2 h3 = __floats2half2_rn(b.z, b.w);
    uint4 o;
    o.x = *reinterpret_cast<unsigned*>(&h0);
    o.y = *reinterpret_cast<unsigned*>(&h1);
    o.z = *reinterpret_cast<unsigned*>(&h2);
    o.w = *reinterpret_cast<unsigned*>(&h3);
    reinterpret_cast<uint4*>(g_Ah)[gid] = o;
}

// ---------------- zero init ----------------
__global__ void k_zero() {
    int idx = blockIdx.x * blockDim.x + threadIdx.x;
    if (idx < BN) {
        g_x[idx] = 0.f; g_xbar[idx] = 0.f;
        g_yb[0][0][idx] = 0.f; g_yb[0][1][idx] = 0.f;
    }
}

// ---------------- TV stencil ----------------
__global__ void k_tv(int bi) {
    int idx = blockIdx.x * blockDim.x + threadIdx.x;
    if (idx >= BN) return;
    int p = idx & (NN - 1);
    int i = p >> 7;
    int j = p & 127;

    const float* yx = g_yb[bi][0];
    const float* yy = g_yb[bi][1];
    float*       oyx = g_yb[bi ^ 1][0];
    float*       oyy = g_yb[bi ^ 1][1];

    float yxv = yx[idx];
    float yyv = yy[idx];

    float dx = (j > 0)  ? (yxv - yx[idx - 1])  : 0.f;
    float dy = (i > 0)  ? (yyv - yy[idx - WW]) : 0.f;
    g_t[idx] = g_x[idx] - TAUF * (dx + dy);

    float xb = g_xbar[idx];
    float gx = (j < WW - 1) ? (xb - g_xbar[idx + 1])  : 0.f;
    float gy = (i < HH - 1) ? (xb - g_xbar[idx + WW]) : 0.f;

    float nyx = yxv + TAUF * gx;
    float nyy = yyv + TAUF * gy;
    float denom = fmaxf(fabsf(nyx), fabsf(nyy)) + EPSF;
    float inv = 1.f / denom;
    oyx[idx] = nyx * inv;
    oyy[idx] = nyy * inv;
}

// ---------------- phase 1: rpart[kc][i][b] = sum_{j in chunk} A[i][j]*t[b][j] ----
// grid (MM/32, KC1); 256 threads; warp = 4 rows; lane owns 8 consecutive cols.
// R3 structure + 2-deep A register double-buffer (no other register pressure).
__global__ __launch_bounds__(256, 2) void k_gemv1() {
    __shared__ ull ts[8 * 512];          // 8 batches x 512 pairs = 32 KB
    int tid = threadIdx.x;
    int lane = tid & 31;
    int g = tid >> 5;
    int r0 = blockIdx.x * 32 + g * 4;
    int k0 = blockIdx.y * 4096;

    const __half* ap = g_Ah + (size_t)r0 * NN + k0;

    ull acc[4][8];
#pragma unroll
    for (int rr = 0; rr < 4; rr++)
#pragma unroll
        for (int b = 0; b < 8; b++) acc[rr][b] = 0ull;

    const int Xsw = (lane >> 2) & 3;     // pair swizzle for this lane

    uint4 av[2][4];                      // A double buffer (4 rows each)

#define ALOADX(DST, G)                                                        \
    {                                                                         \
        int col = (G) * 256 + lane * 8;                                       \
        _Pragma("unroll")                                                     \
        for (int rr = 0; rr < 4; rr++)                                        \
            av[DST][rr] = *reinterpret_cast<const uint4*>(                    \
                ap + (size_t)rr * NN + col);                                  \
    }

    ALOADX(0, 0);                        // prologue

    for (int tt = 0; tt < 4; tt++) {     // 4 tiles of 1024 cols
        __syncthreads();
        int kt = k0 + tt * 1024;
        int P0 = tid * 2;
        int P0s = P0 ^ ((P0 >> 4) & 3);
        int P1 = P0 + 1;
        int P1s = P1 ^ ((P1 >> 4) & 3);
#pragma unroll
        for (int b = 0; b < 8; b++) {
            float4 v = *reinterpret_cast<const float4*>(&g_t[b * NN + kt + tid * 4]);
            ts[b * 512 + P0s] = pack2(v.x, v.y);
            ts[b * 512 + P1s] = pack2(v.z, v.w);
        }
        __syncthreads();

#pragma unroll
        for (int s = 0; s < 4; s++) {
            int gg = tt * 4 + s;
            if (gg < 15) { ALOADX((gg + 1) & 1, gg + 1); }   // prefetch next step
            const uint4* a = av[gg & 1];
            int Pb = s * 128 + lane * 4;

#pragma unroll
            for (int p = 0; p < 4; p++) {
                int Ps = (Pb + p) ^ Xsw;
                unsigned ua0 = (p == 0) ? a[0].x : (p == 1) ? a[0].y : (p == 2) ? a[0].z : a[0].w;
                unsigned ua1 = (p == 0) ? a[1].x : (p == 1) ? a[1].y : (p == 2) ? a[1].z : a[1].w;
                unsigned ua2 = (p == 0) ? a[2].x : (p == 1) ? a[2].y : (p == 2) ? a[2].z : a[2].w;
                unsigned ua3 = (p == 0) ? a[3].x : (p == 1) ? a[3].y : (p == 2) ? a[3].z : a[3].w;
                ull a20 = h2u_to_f32x2(ua0);
                ull a21 = h2u_to_f32x2(ua1);
                ull a22 = h2u_to_f32x2(ua2);
                ull a23 = h2u_to_f32x2(ua3);
#pragma unroll
                for (int b = 0; b < 8; b++) {
                    ull tv = ts[b * 512 + Ps];
                    acc[0][b] = fma2(a20, tv, acc[0][b]);
                    acc[1][b] = fma2(a21, tv, acc[1][b]);
                    acc[2][b] = fma2(a22, tv, acc[2][b]);
                    acc[3][b] = fma2(a23, tv, acc[3][b]);
                }
            }
        }
    }
#undef ALOADX

#pragma unroll
    for (int rr = 0; rr < 4; rr++) {
#pragma unroll
        for (int b = 0; b < 8; b++) {
            float2 f = unpack2(acc[rr][b]);
            float v = f.x + f.y;
            v += __shfl_xor_sync(0xffffffffu, v, 16);
            v += __shfl_xor_sync(0xffffffffu, v, 8);
            v += __shfl_xor_sync(0xffffffffu, v, 4);
            v += __shfl_xor_sync(0xffffffffu, v, 2);
            v += __shfl_xor_sync(0xffffffffu, v, 1);
            if (lane == 0)
                g_rpart[blockIdx.y][r0 + rr][b] = v;
        }
    }
}

// ---------------- phase 2: gpart[blk][b][j] = sum_{i in block} r[b][i]*A[i][j] ----
// grid (NN/1024, RB2); 128 threads; thread owns 8 consecutive cols (uint4 loads).
__global__ __launch_bounds__(128, 4) void k_gemv2(const float* __restrict__ meas) {
    __shared__ ull r2s[128 * 8];          // (row, batch) -> (r,r) packed, 8 KB
    int tid = threadIdx.x;
    int c0 = blockIdx.x * 1024;
    int i0 = blockIdx.y * 128;

#pragma unroll
    for (int k = 0; k < 8; k++) {
        int e = tid + k * 128;            // e = il*8 + b, 1024 entries
        int il = e >> 3, b = e & 7;
        int i = i0 + il;
        float v = -meas[b * MM + i];
#pragma unroll
        for (int kc = 0; kc < KC1; kc++) v += g_rpart[kc][i][b];
        r2s[e] = pack2(v, v);
    }
    __syncthreads();

    const __half* apc = g_Ah + (size_t)i0 * NN + c0 + tid * 8;

    ull acc[4][8];
#pragma unroll
    for (int q = 0; q < 4; q++)
#pragma unroll
        for (int b = 0; b < 8; b++) acc[q][b] = 0ull;

#pragma unroll 4
    for (int i = 0; i < 128; i++) {
        uint4 u = *reinterpret_cast<const uint4*>(apc + (size_t)i * NN);
        ull a0 = h2u_to_f32x2(u.x);
        ull a1 = h2u_to_f32x2(u.y);
        ull a2 = h2u_to_f32x2(u.z);
        ull a3 = h2u_to_f32x2(u.w);
        const ull* rrow = &r2s[i * 8];
#pragma unroll
        for (int b = 0; b < 8; b++) {
            ull rv = rrow[b];             // broadcast LDS
            acc[0][b] = fma2(a0, rv, acc[0][b]);
            acc[1][b] = fma2(a1, rv, acc[1][b]);
            acc[2][b] = fma2(a2, rv, acc[2][b]);
            acc[3][b] = fma2(a3, rv, acc[3][b]);
        }
    }

    int c = c0 + tid * 8;
#pragma unroll
    for (int b = 0; b < 8; b++) {
        float2 f0 = unpack2(acc[0][b]);
        float2 f1 = unpack2(acc[1][b]);
        float2 f2 = unpack2(acc[2][b]);
        float2 f3 = unpack2(acc[3][b]);
        float* dst = &g_gpart[((size_t)(blockIdx.y * 8 + b)) * NN + c];
        *reinterpret_cast<float4*>(dst)     = make_float4(f0.x, f0.y, f1.x, f1.y);
        *reinterpret_cast<float4*>(dst + 4) = make_float4(f2.x, f2.y, f3.x, f3.y);
    }
}

// ---------------- finish: x = t - grad ; xbar = 2x - xbar_old ----------------
__global__ void k_fin() {
    int idx = blockIdx.x * blockDim.x + threadIdx.x;
    if (idx >= BN) return;
    int b = idx >> 14;
    int j = idx & (NN - 1);
    float s = 0.f;
#pragma unroll
    for (int blk = 0; blk < RB2; blk++)
        s += g_gpart[((size_t)(blk * 8 + b)) * NN + j];
    float xn = g_t[idx] - s;
    float xbo = g_xbar[idx];
    g_x[idx] = xn;
    g_xbar[idx] = 2.f * xn - xbo;
}

// ---------------- output copy ----------------
__global__ void k_copy(float* __restrict__ out) {
    int idx = blockIdx.x * blockDim.x + threadIdx.x;
    if (idx < BN) out[idx] = g_x[idx];
}

// ---------------- launch ----------------
extern "C" void kernel_launch(void* const* d_in, const int* in_sizes, int n_in,
                              void* d_out, int out_size) {
    const float* meas = (const float*)d_in[0];
    const float* A    = (const float*)d_in[1];
    if (n_in >= 2 && in_sizes[0] != BB * MM) {
        meas = (const float*)d_in[1];
        A    = (const float*)d_in[0];
    }
    float* out = (float*)d_out;

    k_convert<<<(int)(((size_t)MM * NN) / 8 / 256), 256>>>(A);
    k_zero<<<BN / 256, 256>>>();

    for (int it = 0; it < ITERS; it++) {
        int bi = it & 1;
        k_tv<<<BN / 256, 256>>>(bi);
        k_gemv1<<<dim3(MM / 32, KC1), 256>>>();
        k_gemv2<<<dim3(NN / 1024, RB2), 128>>>(meas);
        k_fin<<<BN / 256, 256>>>();
    }
    k_copy<<<BN / 256, 256>>>(out);
}

// round 6
// speedup vs baseline: 1.5949x; 1.0942x over previous
#include <cuda_runtime.h>
#include <cuda_fp16.h>

typedef unsigned long long ull;

#define BB   8
#define MM   4096
#define NN   16384
#define HH   128
#define WW   128
#define BN   (BB*NN)
#define TAUF 0.01f
#define EPSF 1e-8f
#define ITERS 100

#define KC1   2          // gemv1 K-chunks (8192 cols each)
#define RB2   32         // gemv2 row-blocks (128 rows each)

#define SMEM1 (32768 + 65536)   // gemv1: ts 32KB + A ring 64KB
#define SMEM2 (8192  + 65536)   // gemv2: r2s 8KB + A ring 64KB

// ---------------- device state (no allocations allowed) ----------------
__device__ __half g_Ah[(size_t)MM * NN];          // A in fp16, 128 MB
__device__ float  g_x[BN];
__device__ float  g_xbar[BN];
__device__ float  g_t[BN];
__device__ float  g_yb[2][2][BN];                 // ping-pong y
__device__ float  g_rpart[KC1][MM][BB];           // phase-1 K-split partials
__device__ float  g_gpart[(size_t)RB2 * BB * NN]; // phase-2 M-split partials (16 MB)

// ---------------- helpers ----------------
__device__ __forceinline__ ull pack2(float x, float y) {
    ull r;
    asm("mov.b64 %0, {%1, %2};" : "=l"(r) : "f"(x), "f"(y));
    return r;
}
__device__ __forceinline__ float2 unpack2(ull v) {
    float x, y;
    asm("mov.b64 {%0, %1}, %2;" : "=f"(x), "=f"(y) : "l"(v));
    return make_float2(x, y);
}
__device__ __forceinline__ ull fma2(ull a, ull b, ull c) {
    ull d;
    asm("fma.rn.f32x2 %0, %1, %2, %3;" : "=l"(d) : "l"(a), "l"(b), "l"(c));
    return d;
}
__device__ __forceinline__ ull h2u_to_f32x2(unsigned u) {
    __half2 h = *reinterpret_cast<__half2*>(&u);
    float2 f = __half22float2(h);
    return pack2(f.x, f.y);
}
__device__ __forceinline__ unsigned smem_u32(const void* p) {
    return (unsigned)__cvta_generic_to_shared(p);
}

#define CP_ASYNC16(DST, SRC) \
    asm volatile("cp.async.cg.shared.global [%0], [%1], 16;" :: "r"(DST), "l"(SRC))
#define CP_COMMIT() asm volatile("cp.async.commit_group;" ::: "memory")
#define CP_WAIT3()  asm volatile("cp.async.wait_group 3;" ::: "memory")

// ---------------- A fp32 -> fp16 conversion ----------------
__global__ void k_convert(const float* __restrict__ A) {
    size_t gid = (size_t)blockIdx.x * blockDim.x + threadIdx.x;
    size_t base = gid * 8;
    float4 a = *reinterpret_cast<const float4*>(A + base);
    float4 b = *reinterpret_cast<const float4*>(A + base + 4);
    __half2 h0 = __floats2half2_rn(a.x, a.y);
    __half2 h1 = __floats2half2_rn(a.z, a.w);
    __half2 h2 = __floats2half2_rn(b.x, b.y);
    __half2 h3 = __floats2half2_rn(b.z, b.w);
    uint4 o;
    o.x = *reinterpret_cast<unsigned*>(&h0);
    o.y = *reinterpret_cast<unsigned*>(&h1);
    o.z = *reinterpret_cast<unsigned*>(&h2);
    o.w = *reinterpret_cast<unsigned*>(&h3);
    reinterpret_cast<uint4*>(g_Ah)[gid] = o;
}

// ---------------- zero init ----------------
__global__ void k_zero() {
    int idx = blockIdx.x * blockDim.x + threadIdx.x;
    if (idx < BN) {
        g_x[idx] = 0.f; g_xbar[idx] = 0.f;
        g_yb[0][0][idx] = 0.f; g_yb[0][1][idx] = 0.f;
    }
}

// ---------------- TV stencil ----------------
__global__ void k_tv(int bi) {
    int idx = blockIdx.x * blockDim.x + threadIdx.x;
    if (idx >= BN) return;
    int p = idx & (NN - 1);
    int i = p >> 7;
    int j = p & 127;

    const float* yx = g_yb[bi][0];
    const float* yy = g_yb[bi][1];
    float*       oyx = g_yb[bi ^ 1][0];
    float*       oyy = g_yb[bi ^ 1][1];

    float yxv = yx[idx];
    float yyv = yy[idx];

    float dx = (j > 0)  ? (yxv - yx[idx - 1])  : 0.f;
    float dy = (i > 0)  ? (yyv - yy[idx - WW]) : 0.f;
    g_t[idx] = g_x[idx] - TAUF * (dx + dy);

    float xb = g_xbar[idx];
    float gx = (j < WW - 1) ? (xb - g_xbar[idx + 1])  : 0.f;
    float gy = (i < HH - 1) ? (xb - g_xbar[idx + WW]) : 0.f;

    float nyx = yxv + TAUF * gx;
    float nyy = yyv + TAUF * gy;
    float denom = fmaxf(fabsf(nyx), fabsf(nyy)) + EPSF;
    float inv = 1.f / denom;
    oyx[idx] = nyx * inv;
    oyy[idx] = nyy * inv;
}

// ---------------- phase 1: rpart[kc][i][b] = sum_{j in chunk} A[i][j]*t[b][j] ----
// grid (MM/32, KC1) = (128,2); 256 threads; warp = 4 rows; lane owns 8 cols.
// A streamed via per-lane cp.async 4-stage ring (self-consumed: no barriers).
// Chunk 8192 cols = 8 ts tiles (1024 cols) = 32 stages (256 cols).
__global__ __launch_bounds__(256, 2) void k_gemv1() {
    extern __shared__ char smem_raw[];
    ull*    ts = reinterpret_cast<ull*>(smem_raw);               // 8 x 512 pairs
    __half* As = reinterpret_cast<__half*>(smem_raw + 32768);    // 4 stages x 8192

    int tid = threadIdx.x;
    int lane = tid & 31;
    int g = tid >> 5;
    int r0 = blockIdx.x * 32 + g * 4;
    int k0 = blockIdx.y * 8192;

    const __half* ap = g_Ah + (size_t)r0 * NN + k0 + lane * 8;
    // lane's staging base: As[stage*8192 + g*1024 + rr*256 + lane*8], bytes
    unsigned as_lane = smem_u32(As) + (unsigned)(g * 1024 + lane * 8) * 2;

    ull acc[4][8];
#pragma unroll
    for (int rr = 0; rr < 4; rr++)
#pragma unroll
        for (int b = 0; b < 8; b++) acc[rr][b] = 0ull;

    const int Xsw = (lane >> 2) & 3;

#define ISSUE1(S)                                                             \
    {                                                                         \
        const __half* src = ap + (S) * 256;                                   \
        unsigned dst = as_lane + (unsigned)(((S) & 3) * 8192) * 2;            \
        CP_ASYNC16(dst,        src);                                          \
        CP_ASYNC16(dst + 512,  src + NN);                                     \
        CP_ASYNC16(dst + 1024, src + 2 * NN);                                 \
        CP_ASYNC16(dst + 1536, src + 3 * NN);                                 \
        CP_COMMIT();                                                          \
    }

    ISSUE1(0); ISSUE1(1); ISSUE1(2);

    for (int s = 0; s < 32; s++) {
        if ((s & 3) == 0) {               // stage next 1024-col t tile
            __syncthreads();
            int kt = k0 + (s >> 2) * 1024;
            int P0 = tid * 2;
            int P0s = P0 ^ ((P0 >> 4) & 3);
            int P1 = P0 + 1;
            int P1s = P1 ^ ((P1 >> 4) & 3);
#pragma unroll
            for (int b = 0; b < 8; b++) {
                float4 v = *reinterpret_cast<const float4*>(&g_t[b * NN + kt + tid * 4]);
                ts[b * 512 + P0s] = pack2(v.x, v.y);
                ts[b * 512 + P1s] = pack2(v.z, v.w);
            }
            __syncthreads();
        }

        if (s + 3 < 32) { ISSUE1(s + 3); } else { CP_COMMIT(); }  // keep group count flowing
        CP_WAIT3();                        // stage s resident

        int sb = (s & 3) * 8192 + g * 1024 + lane * 8;
        uint4 a[4];
#pragma unroll
        for (int rr = 0; rr < 4; rr++)
            a[rr] = *reinterpret_cast<const uint4*>(&As[sb + rr * 256]);

        int Pb = (s & 3) * 128 + lane * 4;
#pragma unroll
        for (int p = 0; p < 4; p++) {
            int Ps = (Pb + p) ^ Xsw;
            unsigned ua0 = (p == 0) ? a[0].x : (p == 1) ? a[0].y : (p == 2) ? a[0].z : a[0].w;
            unsigned ua1 = (p == 0) ? a[1].x : (p == 1) ? a[1].y : (p == 2) ? a[1].z : a[1].w;
            unsigned ua2 = (p == 0) ? a[2].x : (p == 1) ? a[2].y : (p == 2) ? a[2].z : a[2].w;
            unsigned ua3 = (p == 0) ? a[3].x : (p == 1) ? a[3].y : (p == 2) ? a[3].z : a[3].w;
            ull a20 = h2u_to_f32x2(ua0);
            ull a21 = h2u_to_f32x2(ua1);
            ull a22 = h2u_to_f32x2(ua2);
            ull a23 = h2u_to_f32x2(ua3);
#pragma unroll
            for (int b = 0; b < 8; b++) {
                ull tv = ts[b * 512 + Ps];
                acc[0][b] = fma2(a20, tv, acc[0][b]);
                acc[1][b] = fma2(a21, tv, acc[1][b]);
                acc[2][b] = fma2(a22, tv, acc[2][b]);
                acc[3][b] = fma2(a23, tv, acc[3][b]);
            }
        }
    }
#undef ISSUE1

#pragma unroll
    for (int rr = 0; rr < 4; rr++) {
#pragma unroll
        for (int b = 0; b < 8; b++) {
            float2 f = unpack2(acc[rr][b]);
            float v = f.x + f.y;
            v += __shfl_xor_sync(0xffffffffu, v, 16);
            v += __shfl_xor_sync(0xffffffffu, v, 8);
            v += __shfl_xor_sync(0xffffffffu, v, 4);
            v += __shfl_xor_sync(0xffffffffu, v, 2);
            v += __shfl_xor_sync(0xffffffffu, v, 1);
            if (lane == 0)
                g_rpart[blockIdx.y][r0 + rr][b] = v;
        }
    }
}

// ---------------- phase 2: gpart[blk][b][j] = sum_{i in block} r[b][i]*A[i][j] ----
// grid (NN/1024, RB2) = (16,32); 128 threads; thread owns 8 cols.
// A streamed via per-thread cp.async 4-stage ring (8 rows/stage, self-consumed).
__global__ __launch_bounds__(128, 3) void k_gemv2(const float* __restrict__ meas) {
    extern __shared__ char smem_raw[];
    ull*    r2s = reinterpret_cast<ull*>(smem_raw);              // 128 x 8
    __half* As  = reinterpret_cast<__half*>(smem_raw + 8192);    // 4 stages x 8192

    int tid = threadIdx.x;
    int c0 = blockIdx.x * 1024;
    int i0 = blockIdx.y * 128;

#pragma unroll
    for (int k = 0; k < 8; k++) {
        int e = tid + k * 128;            // e = il*8 + b
        int il = e >> 3, b = e & 7;
        int i = i0 + il;
        float v = -meas[b * MM + i];
#pragma unroll
        for (int kc = 0; kc < KC1; kc++) v += g_rpart[kc][i][b];
        r2s[e] = pack2(v, v);
    }
    __syncthreads();

    const __half* apc = g_Ah + (size_t)i0 * NN + c0 + tid * 8;
    unsigned as_t = smem_u32(As) + (unsigned)tid * 16;

#define ISSUE2(S)                                                             \
    {                                                                         \
        const __half* src = apc + (size_t)(S) * 8 * NN;                       \
        unsigned dst = as_t + (unsigned)(((S) & 3) * 8192) * 2;               \
        _Pragma("unroll")                                                     \
        for (int j = 0; j < 8; j++)                                           \
            CP_ASYNC16(dst + j * 2048, src + (size_t)j * NN);                 \
        CP_COMMIT();                                                          \
    }

    ull acc[4][8];
#pragma unroll
    for (int q = 0; q < 4; q++)
#pragma unroll
        for (int b = 0; b < 8; b++) acc[q][b] = 0ull;

    ISSUE2(0); ISSUE2(1); ISSUE2(2);

    for (int s = 0; s < 16; s++) {        // 16 stages of 8 rows
        if (s + 3 < 16) { ISSUE2(s + 3); } else { CP_COMMIT(); }
        CP_WAIT3();

        int sb = (s & 3) * 8192 + tid * 8;
#pragma unroll
        for (int j = 0; j < 8; j++) {
            uint4 u = *reinterpret_cast<const uint4*>(&As[sb + j * 1024]);
            ull a0 = h2u_to_f32x2(u.x);
            ull a1 = h2u_to_f32x2(u.y);
            ull a2 = h2u_to_f32x2(u.z);
            ull a3 = h2u_to_f32x2(u.w);
            const ull* rrow = &r2s[(s * 8 + j) * 8];
#pragma unroll
            for (int b = 0; b < 8; b++) {
                ull rv = rrow[b];         // broadcast LDS
                acc[0][b] = fma2(a0, rv, acc[0][b]);
                acc[1][b] = fma2(a1, rv, acc[1][b]);
                acc[2][b] = fma2(a2, rv, acc[2][b]);
                acc[3][b] = fma2(a3, rv, acc[3][b]);
            }
        }
    }
#undef ISSUE2

    int c = c0 + tid * 8;
#pragma unroll
    for (int b = 0; b < 8; b++) {
        float2 f0 = unpack2(acc[0][b]);
        float2 f1 = unpack2(acc[1][b]);
        float2 f2 = unpack2(acc[2][b]);
        float2 f3 = unpack2(acc[3][b]);
        float* dst = &g_gpart[((size_t)(blockIdx.y * 8 + b)) * NN + c];
        *reinterpret_cast<float4*>(dst)     = make_float4(f0.x, f0.y, f1.x, f1.y);
        *reinterpret_cast<float4*>(dst + 4) = make_float4(f2.x, f2.y, f3.x, f3.y);
    }
}

// ---------------- finish: x = t - grad ; xbar = 2x - xbar_old ----------------
__global__ void k_fin() {
    int idx = blockIdx.x * blockDim.x + threadIdx.x;
    if (idx >= BN) return;
    int b = idx >> 14;
    int j = idx & (NN - 1);
    float s = 0.f;
#pragma unroll
    for (int blk = 0; blk < RB2; blk++)
        s += g_gpart[((size_t)(blk * 8 + b)) * NN + j];
    float xn = g_t[idx] - s;
    float xbo = g_xbar[idx];
    g_x[idx] = xn;
    g_xbar[idx] = 2.f * xn - xbo;
}

// ---------------- output copy ----------------
__global__ void k_copy(float* __restrict__ out) {
    int idx = blockIdx.x * blockDim.x + threadIdx.x;
    if (idx < BN) out[idx] = g_x[idx];
}

// ---------------- launch ----------------
extern "C" void kernel_launch(void* const* d_in, const int* in_sizes, int n_in,
                              void* d_out, int out_size) {
    const float* meas = (const float*)d_in[0];
    const float* A    = (const float*)d_in[1];
    if (n_in >= 2 && in_sizes[0] != BB * MM) {
        meas = (const float*)d_in[1];
        A    = (const float*)d_in[0];
    }
    float* out = (float*)d_out;

    cudaFuncSetAttribute(k_gemv1, cudaFuncAttributeMaxDynamicSharedMemorySize, SMEM1);
    cudaFuncSetAttribute(k_gemv2, cudaFuncAttributeMaxDynamicSharedMemorySize, SMEM2);

    k_convert<<<(int)(((size_t)MM * NN) / 8 / 256), 256>>>(A);
    k_zero<<<BN / 256, 256>>>();

    for (int it = 0; it < ITERS; it++) {
        int bi = it & 1;
        k_tv<<<BN / 256, 256>>>(bi);
        k_gemv1<<<dim3(MM / 32, KC1), 256, SMEM1>>>();
        k_gemv2<<<dim3(NN / 1024, RB2), 128, SMEM2>>>(meas);
        k_fin<<<BN / 256, 256>>>();
    }
    k_copy<<<BN / 256, 256>>>(out);
}

// round 8
// speedup vs baseline: 2.4176x; 1.5158x over previous
#include <cuda_runtime.h>
#include <cuda_fp16.h>
#include <cstdint>

#define BB   8
#define MM   4096
#define NN   16384
#define HH   128
#define WW   128
#define BN   (BB*NN)
#define TAUF 0.01f
#define EPSF 1e-8f
#define ITERS 100

#define KC1    8            // phase-1 K chunks (16384/8 = 2048)
#define KC2    2            // phase-2 K chunks (4096/2 = 2048)
#define KCHUNK 2048
#define NSTEPS 32           // KCHUNK / 64 cols per stage

// smem layout for k_mma
#define SM_A     0          // 4 stages x 16384 B  (A tile 128 rows x 128 B, SW128)
#define SM_B     65536      // 4 stages x 2048 B   (B tile 16 rows x 128 B, SW128)
#define SM_TOTAL 73728

// ---------------- device state (no allocations allowed) ----------------
__device__ __half g_Ah [(size_t)MM * NN];     // A fp16 row-major [i][j]
__device__ __half g_AhT[(size_t)MM * NN];     // A^T fp16 [j][i]
__device__ float  g_x[BN];
__device__ float  g_xbar[BN];
__device__ float  g_t[BN];
__device__ float  g_yb[2][2][BN];
__device__ __half g_t16[(size_t)16 * NN];     // rows 0-7 = hi(t), 8-15 = lo(t)*2048
__device__ __half g_r16[(size_t)16 * MM];     // rows 0-7 = hi(r), 8-15 = lo(r)*2048
__device__ float  g_rpart[(size_t)KC1 * MM * 8];   // phase-1 partials [kc][i][b]
__device__ float  g_gpart[(size_t)KC2 * NN * 8];   // phase-2 partials [kc][j][b]

// ---------------- helpers ----------------
#define SWZ(o) ((o) ^ (((o) >> 3) & 0x70))

#define CP16(DST, SRC) \
    asm volatile("cp.async.cg.shared.global [%0], [%1], 16;" :: "r"(DST), "l"(SRC))
#define CP_COMMIT() asm volatile("cp.async.commit_group;" ::: "memory")
#define CP_WAIT2()  asm volatile("cp.async.wait_group 2;"  ::: "memory")

#define LDM_X4(R0, R1, R2, R3, ADDR)                                          \
    asm volatile("ldmatrix.sync.aligned.m8n8.x4.shared.b16 {%0,%1,%2,%3}, [%4];" \
                 : "=r"(R0), "=r"(R1), "=r"(R2), "=r"(R3) : "r"(ADDR))

#define MMA16816(C, A0, A1, A2, A3, B0, B1)                                   \
    asm volatile("mma.sync.aligned.m16n8k16.row.col.f32.f16.f16.f32 "         \
                 "{%0,%1,%2,%3}, {%4,%5,%6,%7}, {%8,%9}, {%0,%1,%2,%3};"      \
                 : "+f"((C)[0]), "+f"((C)[1]), "+f"((C)[2]), "+f"((C)[3])     \
                 : "r"(A0), "r"(A1), "r"(A2), "r"(A3), "r"(B0), "r"(B1))

// ---------------- setup: A fp32 -> fp16 + fp16 transpose (one-time) ----------
__global__ void k_setup(const float* __restrict__ A) {
    __shared__ __half tile[32][33];
    int j0 = blockIdx.x * 32, i0 = blockIdx.y * 32;
    int tx = threadIdx.x, ty = threadIdx.y;          // (32, 8)
#pragma unroll
    for (int q = 0; q < 4; q++) {
        int il = ty + q * 8;
        float v = A[(size_t)(i0 + il) * NN + j0 + tx];
        __half h = __float2half_rn(v);
        g_Ah[(size_t)(i0 + il) * NN + j0 + tx] = h;
        tile[il][tx] = h;
    }
    __syncthreads();
#pragma unroll
    for (int q = 0; q < 4; q++) {
        int jl = ty + q * 8;
        g_AhT[(size_t)(j0 + jl) * MM + i0 + tx] = tile[tx][jl];
    }
}

// ---------------- zero init ----------------
__global__ void k_zero() {
    int idx = blockIdx.x * blockDim.x + threadIdx.x;
    if (idx < BN) {
        g_x[idx] = 0.f; g_xbar[idx] = 0.f;
        g_yb[0][0][idx] = 0.f; g_yb[0][1][idx] = 0.f;
    }
}

// ---------------- TV stencil + t16 hi/lo emit ----------------
__global__ void k_tv(int bi) {
    int idx = blockIdx.x * blockDim.x + threadIdx.x;
    if (idx >= BN) return;
    int p = idx & (NN - 1);
    int i = p >> 7;
    int j = p & 127;

    const float* yx = g_yb[bi][0];
    const float* yy = g_yb[bi][1];
    float*       oyx = g_yb[bi ^ 1][0];
    float*       oyy = g_yb[bi ^ 1][1];

    float yxv = yx[idx];
    float yyv = yy[idx];

    float dx = (j > 0) ? (yxv - yx[idx - 1])  : 0.f;
    float dy = (i > 0) ? (yyv - yy[idx - WW]) : 0.f;
    float t = g_x[idx] - TAUF * (dx + dy);
    g_t[idx] = t;

    __half hi = __float2half_rn(t);
    float  lo = (t - __half2float(hi)) * 2048.f;
    g_t16[idx] = hi;                          // row b = idx>>14, col = idx&16383
    g_t16[(size_t)BN + idx] = __float2half_rn(lo);

    float xb = g_xbar[idx];
    float gx = (j < WW - 1) ? (xb - g_xbar[idx + 1])  : 0.f;
    float gy = (i < HH - 1) ? (xb - g_xbar[idx + WW]) : 0.f;

    float nyx = yxv + TAUF * gx;
    float nyy = yyv + TAUF * gy;
    float denom = fmaxf(fabsf(nyx), fabsf(nyy)) + EPSF;
    float inv = 1.f / denom;
    oyx[idx] = nyx * inv;
    oyy[idx] = nyy * inv;
}

// ---------------- unified HMMA GEMV kernel -----------------------------------
// phase 0: D[i,b16] += A[i,k]  * t16[b16,k]  (g_Ah,  K=NN, M=MM, grid (32,KC1))
// phase 1: D[j,b16] += AT[j,k] * r16[b16,k]  (g_AhT, K=MM, M=NN, grid (128,KC2))
// CTA: 128 rows x 2048-col K chunk = 32 stages of 64 cols.
// Stage: A 128x64 f16 (16KB SW128) + B 16x64 f16 (2KB SW128) via cp.async.
// Warp w owns rows w*32..+32 (2 m16 tiles); N=16 = hi(8)+lo(8) batches.
__global__ __launch_bounds__(128) void k_mma(int phase) {
    extern __shared__ char sm[];
    unsigned smb = (unsigned)__cvta_generic_to_shared(sm);
    int tid = threadIdx.x, wid = tid >> 5, lane = tid & 31;

    const __half* Aop = phase ? g_AhT : g_Ah;
    const __half* Bop = phase ? g_r16 : g_t16;
    float*        outp = phase ? g_gpart : g_rpart;
    const int Ktot = phase ? MM : NN;
    const int Mtot = phase ? NN : MM;

    int r0 = blockIdx.x * 128;
    int k0 = blockIdx.y * KCHUNK;

    // ---- stage fill: 9 x 16B cp.async per thread ----
    auto fill = [&](int s) {
        int slot = s & 3;
        const __half* asrc = Aop + (size_t)r0 * Ktot + k0 + s * 64;
        unsigned abase = smb + SM_A + slot * 16384;
#pragma unroll
        for (int q = 0; q < 8; q++) {
            int c = tid + q * 128;
            int row = c >> 3, c16 = c & 7;
            unsigned off = (unsigned)(row * 128 + c16 * 16);
            CP16(abase + SWZ(off), asrc + (size_t)row * Ktot + c16 * 8);
        }
        const __half* bsrc = Bop + k0 + s * 64;
        int brow = tid >> 3, bc16 = tid & 7;
        unsigned boff = (unsigned)(brow * 128 + bc16 * 16);
        CP16(smb + SM_B + slot * 2048 + SWZ(boff), bsrc + (size_t)brow * Ktot + bc16 * 8);
        CP_COMMIT();
    };

    float c[2][2][4];
#pragma unroll
    for (int mt = 0; mt < 2; mt++)
#pragma unroll
        for (int nt = 0; nt < 2; nt++)
#pragma unroll
            for (int q = 0; q < 4; q++) c[mt][nt][q] = 0.f;

    fill(0); fill(1); fill(2);

    int l8 = lane & 7;
    int lq = lane >> 3;                  // ldmatrix quadrant 0..3

    for (int s = 0; s < NSTEPS; s++) {
        CP_WAIT2();
        __syncthreads();                 // stage s visible; stage s-1 consumption done

        int ns = s + 3;
        if (ns < NSTEPS) { fill(ns); } else { CP_COMMIT(); }

        int slot = s & 3;
        unsigned abase = smb + SM_A + slot * 16384;
        unsigned bbase = smb + SM_B + slot * 2048;

#pragma unroll
        for (int kk = 0; kk < 4; kk++) {
            // B frags: matrices [n0-7,k0-7],[n0-7,k8-15],[n8-15,k0-7],[n8-15,k8-15]
            unsigned brow = (lq >> 1) * 8 + l8;
            unsigned bcol = kk * 32 + (lq & 1) * 16;
            unsigned b0, b1, b2, b3;
            LDM_X4(b0, b1, b2, b3, bbase + SWZ(brow * 128 + bcol));

#pragma unroll
            for (int mt = 0; mt < 2; mt++) {
                // A frags: [r0-7,k0-7],[r8-15,k0-7],[r0-7,k8-15],[r8-15,k8-15]
                unsigned arow = wid * 32 + mt * 16 + (lq & 1) * 8 + l8;
                unsigned acol = kk * 32 + (lq >> 1) * 16;
                unsigned a0, a1, a2, a3;
                LDM_X4(a0, a1, a2, a3, abase + SWZ(arow * 128 + acol));

                MMA16816(c[mt][0], a0, a1, a2, a3, b0, b1);   // hi batches
                MMA16816(c[mt][1], a0, a1, a2, a3, b2, b3);   // lo batches
            }
        }
    }

    // ---- epilogue: fold hi + lo/2048, write partials ----
    int g = lane >> 2, t4 = lane & 3;
#pragma unroll
    for (int mt = 0; mt < 2; mt++) {
        int row = r0 + wid * 32 + mt * 16 + g;
        float* d0 = outp + ((size_t)blockIdx.y * Mtot + row) * 8 + t4 * 2;
        float* d1 = outp + ((size_t)blockIdx.y * Mtot + row + 8) * 8 + t4 * 2;
        const float is = 1.f / 2048.f;
        *reinterpret_cast<float2*>(d0) = make_float2(
            c[mt][0][0] + c[mt][1][0] * is, c[mt][0][1] + c[mt][1][1] * is);
        *reinterpret_cast<float2*>(d1) = make_float2(
            c[mt][0][2] + c[mt][1][2] * is, c[mt][0][3] + c[mt][1][3] * is);
    }
}

// ---------------- r prep: r = sum(rpart) - meas -> hi/lo fp16 ----------------
__global__ void k_rprep(const float* __restrict__ meas) {
    int idx = blockIdx.x * blockDim.x + threadIdx.x;   // 32768
    int i = idx >> 3, b = idx & 7;
    float v = -meas[b * MM + i];
#pragma unroll
    for (int kc = 0; kc < KC1; kc++)
        v += g_rpart[((size_t)kc * MM + i) * 8 + b];
    __half hi = __float2half_rn(v);
    float  lo = (v - __half2float(hi)) * 2048.f;
    g_r16[(size_t)b * MM + i] = hi;
    g_r16[(size_t)(b + 8) * MM + i] = __float2half_rn(lo);
}

// ---------------- finish: x = t - grad ; xbar = 2x - xbar_old ----------------
__global__ void k_fin() {
    int idx = blockIdx.x * blockDim.x + threadIdx.x;
    if (idx >= BN) return;
    int b = idx >> 14;
    int j = idx & (NN - 1);
    float s = 0.f;
#pragma unroll
    for (int kc = 0; kc < KC2; kc++)
        s += g_gpart[((size_t)kc * NN + j) * 8 + b];
    float xn = g_t[idx] - s;
    float xbo = g_xbar[idx];
    g_x[idx] = xn;
    g_xbar[idx] = 2.f * xn - xbo;
}

// ---------------- output copy ----------------
__global__ void k_copy(float* __restrict__ out) {
    int idx = blockIdx.x * blockDim.x + threadIdx.x;
    if (idx < BN) out[idx] = g_x[idx];
}

// ---------------- launch ----------------
extern "C" void kernel_launch(void* const* d_in, const int* in_sizes, int n_in,
                              void* d_out, int out_size) {
    const float* meas = (const float*)d_in[0];
    const float* A    = (const float*)d_in[1];
    if (n_in >= 2 && in_sizes[0] != BB * MM) {
        meas = (const float*)d_in[1];
        A    = (const float*)d_in[0];
    }
    float* out = (float*)d_out;

    cudaFuncSetAttribute(k_mma, cudaFuncAttributeMaxDynamicSharedMemorySize, SM_TOTAL);

    k_setup<<<dim3(NN / 32, MM / 32), dim3(32, 8)>>>(A);
    k_zero<<<BN / 256, 256>>>();

    for (int it = 0; it < ITERS; it++) {
        int bi = it & 1;
        k_tv<<<BN / 256, 256>>>(bi);
        k_mma<<<dim3(MM / 128, KC1), 128, SM_TOTAL>>>(0);
        k_rprep<<<(MM * 8) / 256, 256>>>(meas);
        k_mma<<<dim3(NN / 128, KC2), 128, SM_TOTAL>>>(1);
        k_fin<<<BN / 256, 256>>>();
    }
    k_copy<<<BN / 256, 256>>>(out);
}